// round 11
// baseline (speedup 1.0000x reference)
#include <cuda_runtime.h>
#include <cuda_fp16.h>
#include <cstdint>

// ============================================================================
// Problem constants
// ============================================================================
#define NQ        1024
#define DDIM      512
#define MROWS     262144
#define BANK_TILE 64           // bank rows per CTA (2 CTAs/SM)
#define MEGA      256          // queries per pass
#define NPASS     4
#define KCH       16           // k-chunks of 32 dims per pass
#define NCHUNK    64
#define THREADS   256
#define NCTAS     (MROWS / BANK_TILE)   // 4096
#define PREP_CTAS 128

// smem layout. Row pads: 8-row ldmatrix strides hit distinct 16B groups.
#define BANK_RS    1040                           // 512 fp16 + 16B pad
#define QBUF_RS    80                             // 32 fp16 + 16B pad
#define SMEM_BANK  0
#define BANK_SZ    (BANK_TILE * BANK_RS)          // 66560
#define SMEM_QBUF  BANK_SZ
#define QBUF_SZ    (MEGA * QBUF_RS)               // 20480
#define SMEM_TOTAL (SMEM_QBUF + 2 * QBUF_SZ)      // 107520 -> 2 CTAs/SM

__device__ __align__(1024) __half g_qh[NQ * DDIM];
__device__ unsigned g_key[NQ];
__device__ volatile unsigned g_prep_done;   // prep-CTA arrival count
__device__ unsigned g_done;                 // finished-CTA count

// ============================================================================
// Helpers
// ============================================================================
__device__ __forceinline__ uint32_t smem_to_u32(const void* p) {
    uint32_t a;
    asm("{ .reg .u64 t; cvta.to.shared.u64 t, %1; cvt.u32.u64 %0, t; }" : "=r"(a) : "l"(p));
    return a;
}

#define CP_ASYNC16(dst_u32, src_gptr) \
    asm volatile("cp.async.cg.shared.global [%0], [%1], 16;" :: "r"(dst_u32), "l"(src_gptr) : "memory")
#define CP_ASYNC_COMMIT() asm volatile("cp.async.commit_group;" ::: "memory")
#define CP_ASYNC_WAIT(n)  asm volatile("cp.async.wait_group %0;" :: "n"(n) : "memory")

#define LDMATRIX_X4(r0, r1, r2, r3, addr) \
    asm volatile("ldmatrix.sync.aligned.m8n8.x4.shared.b16 {%0,%1,%2,%3}, [%4];" \
        : "=r"(r0), "=r"(r1), "=r"(r2), "=r"(r3) : "r"(addr))

__device__ __forceinline__ void mma16816h(uint32_t* d, const uint32_t* a, uint32_t b0, uint32_t b1) {
    asm volatile(
        "mma.sync.aligned.m16n8k16.row.col.f16.f16.f16.f16 "
        "{%0,%1}, {%2,%3,%4,%5}, {%6,%7}, {%0,%1};"
        : "+r"(d[0]), "+r"(d[1])
        : "r"(a[0]), "r"(a[1]), "r"(a[2]), "r"(a[3]), "r"(b0), "r"(b1));
}

__device__ __forceinline__ __half2 u2h2(uint32_t u) { return *reinterpret_cast<__half2*>(&u); }
__device__ __forceinline__ uint32_t h22u(__half2 h) { return *reinterpret_cast<uint32_t*>(&h); }

__device__ __forceinline__ unsigned enc_key(float f) {
    unsigned b = __float_as_uint(f);
    return (b & 0x80000000u) ? ~b : (b | 0x80000000u);
}

// cp.async loader: chunk j = pass*16 + kc (256 queries x 32 fp16 dims) -> slot
__device__ __forceinline__ void issue_qchunk(uint32_t sb, int tid, int j, int slot) {
    const int pass = j >> 4, kc = j & 15;
    const char* src_base = reinterpret_cast<const char*>(g_qh)
                         + (size_t)(pass * MEGA) * (DDIM * 2) + kc * 64;
    const uint32_t dst_base = sb + (uint32_t)(SMEM_QBUF + slot * QBUF_SZ);
    #pragma unroll
    for (int it = 0; it < 4; ++it) {
        int idx = tid + it * THREADS;          // 1024 granules of 16B (256 rows x 4)
        int n = idx >> 2, t = idx & 3;
        CP_ASYNC16(dst_base + (uint32_t)(n * QBUF_RS + t * 16),
                   src_base + (size_t)n * (DDIM * 2) + t * 16);
    }
    CP_ASYNC_COMMIT();
}

// ============================================================================
// Single fused kernel: prep (CTAs 0..127) -> flag -> GEMM+max -> last CTA
// decodes. Warp tile m64 x n32 (192 B LDSM per MMA, crossbar at 75%).
// ============================================================================
__global__ void __launch_bounds__(THREADS, 2)
patchcore_all(const float* __restrict__ feat, const float* __restrict__ bank,
              float* __restrict__ out) {
    extern __shared__ char smem[];
    __shared__ unsigned s_last;
    const uint32_t sb = smem_to_u32(smem);
    const int tid  = threadIdx.x;
    const int w    = tid >> 5;
    const int lane = tid & 31;
    const int wm   = w & 3;        // m-offset wm*64 (queries)
    const int wn   = w >> 2;       // n-offset wn*32 (bank rows)
    const size_t m0 = (size_t)blockIdx.x * BANK_TILE;

    // ---- Bank tile (64 x 512 fp32) -> fp16 smem (independent of queries) ----
    {
        const float4* src = reinterpret_cast<const float4*>(bank);
        #pragma unroll 4
        for (int idx = tid; idx < BANK_TILE * (DDIM / 4); idx += THREADS) {
            int m = idx >> 7;
            int c4 = idx & 127;
            float4 v = src[((m0 + (size_t)m) << 7) + c4];
            uint2 p;
            p.x = h22u(__floats2half2_rn(v.x, v.y));
            p.y = h22u(__floats2half2_rn(v.z, v.w));
            *reinterpret_cast<uint2*>(smem + (SMEM_BANK + m * BANK_RS + c4 * 8)) = p;
        }
    }

    // ---- Prep: CTAs 0..127 normalize 8 queries each (warp per query) ----
    if (blockIdx.x < PREP_CTAS) {
        const int q = blockIdx.x * 8 + w;
        const float4* src = reinterpret_cast<const float4*>(feat + (size_t)q * DDIM);
        float4 v[4];
        float ss = 0.0f;
        #pragma unroll
        for (int p = 0; p < 4; ++p) {
            v[p] = src[p * 32 + lane];
            ss += v[p].x * v[p].x + v[p].y * v[p].y + v[p].z * v[p].z + v[p].w * v[p].w;
        }
        #pragma unroll
        for (int o = 16; o > 0; o >>= 1) ss += __shfl_xor_sync(0xFFFFFFFFu, ss, o);
        const float inv = rsqrtf(ss);
        __half2* dst = reinterpret_cast<__half2*>(g_qh + (size_t)q * DDIM);
        #pragma unroll
        for (int p = 0; p < 4; ++p) {
            dst[(p * 32 + lane) * 2 + 0] = __floats2half2_rn(v[p].x * inv, v[p].y * inv);
            dst[(p * 32 + lane) * 2 + 1] = __floats2half2_rn(v[p].z * inv, v[p].w * inv);
        }
        if (lane == 0) g_key[q] = 0u;
        __syncthreads();
        if (tid == 0) {
            __threadfence();                        // release g_qh/g_key
            atomicAdd((unsigned*)&g_prep_done, 1u);
        }
    }

    // ---- Acquire: wait for all prep CTAs (wave 1 holds them all) ----
    if (tid == 0) {
        while (g_prep_done < PREP_CTAS) __nanosleep(64);
        __threadfence();                            // acquire
    }
    __syncthreads();                                // also orders bank smem stores

    // ---- Main GEMM loop: ring-2 query buffer, one barrier per chunk ----
    const uint32_t lm_row = (uint32_t)(lane & 15);
    const uint32_t lm_col = (uint32_t)((lane & 16) ? 16 : 0);
    const uint32_t a_lane = ((uint32_t)(wm * 64) + lm_row) * QBUF_RS + lm_col;
    const uint32_t b_lane = sb + SMEM_BANK + ((uint32_t)(wn * 32) + lm_row) * BANK_RS + lm_col;

    issue_qchunk(sb, tid, 0, 0);
    int j = 0;
    for (int pass = 0; pass < NPASS; ++pass) {
        uint32_t d[4][4][2];                        // [m-tile][n8-tile][row] f16x2
        #pragma unroll
        for (int mt = 0; mt < 4; ++mt)
            #pragma unroll
            for (int nt = 0; nt < 4; ++nt) { d[mt][nt][0] = 0u; d[mt][nt][1] = 0u; }

        for (int kc = 0; kc < KCH; ++kc, ++j) {
            CP_ASYNC_WAIT(0);                       // chunk j landed
            __syncthreads();                        // all warps done with slot j^1
            if (j + 1 < NCHUNK) issue_qchunk(sb, tid, j + 1, (j + 1) & 1);

            const uint32_t abase = sb + (uint32_t)(SMEM_QBUF + (j & 1) * QBUF_SZ) + a_lane;
            const uint32_t bbase = b_lane + (uint32_t)(kc * 64);
            #pragma unroll
            for (int ks = 0; ks < 2; ++ks) {        // 2 x k16 per 32-dim chunk
                uint32_t a[4][4];
                #pragma unroll
                for (int mt = 0; mt < 4; ++mt)
                    LDMATRIX_X4(a[mt][0], a[mt][1], a[mt][2], a[mt][3],
                                abase + (uint32_t)(mt * 16 * QBUF_RS + ks * 32));
                #pragma unroll
                for (int bt = 0; bt < 2; ++bt) {
                    uint32_t b0, b1, b2, b3;        // b0/b2: n8 tile 2bt ; b1/b3: 2bt+1
                    LDMATRIX_X4(b0, b1, b2, b3,
                                bbase + (uint32_t)(bt * 16 * BANK_RS + ks * 32));
                    #pragma unroll
                    for (int mt = 0; mt < 4; ++mt) {
                        mma16816h(d[mt][2 * bt],     a[mt], b0, b2);
                        mma16816h(d[mt][2 * bt + 1], a[mt], b1, b3);
                    }
                }
            }
        }

        // ---- Epilogue: max over this warp's 32 bank rows per query ----
        #pragma unroll
        for (int mt = 0; mt < 4; ++mt) {
            __half2 h0 = u2h2(d[mt][0][0]);
            __half2 h1 = u2h2(d[mt][0][1]);
            #pragma unroll
            for (int nt = 1; nt < 4; ++nt) {
                h0 = __hmax2(h0, u2h2(d[mt][nt][0]));
                h1 = __hmax2(h1, u2h2(d[mt][nt][1]));
            }
            float mx0 = fmaxf(__low2float(h0), __high2float(h0));
            float mx1 = fmaxf(__low2float(h1), __high2float(h1));
            mx0 = fmaxf(mx0, __shfl_xor_sync(0xFFFFFFFFu, mx0, 1));
            mx0 = fmaxf(mx0, __shfl_xor_sync(0xFFFFFFFFu, mx0, 2));
            mx1 = fmaxf(mx1, __shfl_xor_sync(0xFFFFFFFFu, mx1, 1));
            mx1 = fmaxf(mx1, __shfl_xor_sync(0xFFFFFFFFu, mx1, 2));
            if ((lane & 3) == 0) {
                int q0 = pass * MEGA + wm * 64 + mt * 16 + (lane >> 2);
                atomicMax(&g_key[q0],     enc_key(mx0));
                atomicMax(&g_key[q0 + 8], enc_key(mx1));
            }
        }
    }

    // ---- Completion: last CTA decodes keys and resets counters ----
    __threadfence();                                // release atomicMax results
    __syncthreads();
    if (tid == 0) s_last = atomicAdd(&g_done, 1u);
    __syncthreads();
    if (s_last == NCTAS - 1) {
        __threadfence();                            // acquire all g_key updates
        volatile unsigned* keys = (volatile unsigned*)g_key;
        for (int i = tid; i < NQ; i += THREADS) {
            unsigned key = keys[i];
            unsigned bits = (key & 0x80000000u) ? (key ^ 0x80000000u) : ~key;
            float xy = __uint_as_float(bits);
            out[i] = sqrtf(fmaxf(2.0f - 2.0f * xy, 1e-12f));
        }
        __syncthreads();
        if (tid == 0) {                             // reset for next graph replay
            g_done = 0;
            *(unsigned*)&g_prep_done = 0;
        }
    }
}

// ============================================================================
// Launch: one kernel
// ============================================================================
extern "C" void kernel_launch(void* const* d_in, const int* in_sizes, int n_in,
                              void* d_out, int out_size) {
    const float* feat = (const float*)d_in[0];
    const float* bank = (const float*)d_in[1];
    if (n_in >= 2 && in_sizes[0] != NQ * DDIM) {   // robust to input ordering
        feat = (const float*)d_in[1];
        bank = (const float*)d_in[0];
    }
    float* out = (float*)d_out;

    cudaFuncSetAttribute(patchcore_all, cudaFuncAttributeMaxDynamicSharedMemorySize, SMEM_TOTAL);
    patchcore_all<<<NCTAS, THREADS, SMEM_TOTAL>>>(feat, bank, out);
}

// round 12
// speedup vs baseline: 1.1478x; 1.1478x over previous
#include <cuda_runtime.h>
#include <cuda_fp16.h>
#include <cstdint>

// ============================================================================
// Problem constants
// ============================================================================
#define NQ        1024
#define DDIM      512
#define MROWS     262144
#define BANK_TILE 64           // bank rows per CTA (2 CTAs/SM)
#define MEGA      128          // queries per pass
#define NPASS     8
#define KCH       8            // k-chunks of 64 dims per pass
#define NCHUNK    64
#define THREADS   256
#define NCTAS     (MROWS / BANK_TILE)   // 4096
#define PREP_CTAS 128
#define SKEW_CYC  1000

// smem layout. Row pads: 8-row ldmatrix strides hit distinct 16B groups.
#define BANK_RS    1040
#define QBUF_RS    144
#define SMEM_BANK  0
#define BANK_SZ    (BANK_TILE * BANK_RS)          // 66560
#define SMEM_QBUF  BANK_SZ
#define QBUF_SZ    (MEGA * QBUF_RS)               // 18432
#define SMEM_TOTAL (SMEM_QBUF + 2 * QBUF_SZ)      // 103424 -> 2 CTAs/SM

__device__ __align__(1024) __half g_qh[NQ * DDIM];
__device__ unsigned g_key[NQ];
__device__ volatile unsigned g_prep_done;   // prep-CTA arrival count
__device__ unsigned g_done;                 // finished-CTA count
__device__ unsigned g_smrank[256];          // per-SM arrival rank (stagger)

// ============================================================================
// Helpers
// ============================================================================
__device__ __forceinline__ uint32_t smem_to_u32(const void* p) {
    uint32_t a;
    asm("{ .reg .u64 t; cvta.to.shared.u64 t, %1; cvt.u32.u64 %0, t; }" : "=r"(a) : "l"(p));
    return a;
}
__device__ __forceinline__ uint32_t smid() {
    uint32_t s;
    asm("mov.u32 %0, %%smid;" : "=r"(s));
    return s;
}

#define CP_ASYNC16(dst_u32, src_gptr) \
    asm volatile("cp.async.cg.shared.global [%0], [%1], 16;" :: "r"(dst_u32), "l"(src_gptr) : "memory")
#define CP_ASYNC_COMMIT() asm volatile("cp.async.commit_group;" ::: "memory")
#define CP_ASYNC_WAIT(n)  asm volatile("cp.async.wait_group %0;" :: "n"(n) : "memory")

#define LDMATRIX_X4(r0, r1, r2, r3, addr) \
    asm volatile("ldmatrix.sync.aligned.m8n8.x4.shared.b16 {%0,%1,%2,%3}, [%4];" \
        : "=r"(r0), "=r"(r1), "=r"(r2), "=r"(r3) : "r"(addr))

__device__ __forceinline__ void mma16816h(uint32_t* d, const uint32_t* a, uint32_t b0, uint32_t b1) {
    asm volatile(
        "mma.sync.aligned.m16n8k16.row.col.f16.f16.f16.f16 "
        "{%0,%1}, {%2,%3,%4,%5}, {%6,%7}, {%0,%1};"
        : "+r"(d[0]), "+r"(d[1])
        : "r"(a[0]), "r"(a[1]), "r"(a[2]), "r"(a[3]), "r"(b0), "r"(b1));
}

__device__ __forceinline__ __half2 u2h2(uint32_t u) { return *reinterpret_cast<__half2*>(&u); }
__device__ __forceinline__ uint32_t h22u(__half2 h) { return *reinterpret_cast<uint32_t*>(&h); }

__device__ __forceinline__ unsigned enc_key(float f) {
    unsigned b = __float_as_uint(f);
    return (b & 0x80000000u) ? ~b : (b | 0x80000000u);
}

// cp.async loader: chunk j = pass*8 + kc (128 queries x 64 fp16 dims) -> slot
__device__ __forceinline__ void issue_qchunk(uint32_t sb, int tid, int j, int slot) {
    const int pass = j >> 3, kc = j & 7;
    const char* src_base = reinterpret_cast<const char*>(g_qh)
                         + (size_t)(pass * MEGA) * (DDIM * 2) + kc * 128;
    const uint32_t dst_base = sb + (uint32_t)(SMEM_QBUF + slot * QBUF_SZ);
    #pragma unroll
    for (int it = 0; it < 4; ++it) {
        int idx = tid + it * THREADS;          // 1024 granules of 16B
        int n = idx >> 3, t = idx & 7;
        CP_ASYNC16(dst_base + (uint32_t)(n * QBUF_RS + t * 16),
                   src_base + (size_t)n * (DDIM * 2) + t * 16);
    }
    CP_ASYNC_COMMIT();
}

// ============================================================================
// Single fused kernel (R10 engine + same-SM CTA stagger + loader displacement)
// ============================================================================
__global__ void __launch_bounds__(THREADS, 2)
patchcore_all(const float* __restrict__ feat, const float* __restrict__ bank,
              float* __restrict__ out) {
    extern __shared__ char smem[];
    __shared__ unsigned s_last;
    __shared__ unsigned s_rank;
    const uint32_t sb = smem_to_u32(smem);
    const int tid  = threadIdx.x;
    const int w    = tid >> 5;
    const int lane = tid & 31;
    const int wm   = w & 3;        // m-offset wm*32 (queries)
    const int wn   = w >> 2;       // n-offset wn*32 (bank rows)
    const size_t m0 = (size_t)blockIdx.x * BANK_TILE;

    if (tid == 0) s_rank = atomicAdd(&g_smrank[smid() & 255], 1u);

    // ---- Bank tile (64 x 512 fp32) -> fp16 smem (independent of queries) ----
    {
        const float4* src = reinterpret_cast<const float4*>(bank);
        #pragma unroll 4
        for (int idx = tid; idx < BANK_TILE * (DDIM / 4); idx += THREADS) {
            int m = idx >> 7;
            int c4 = idx & 127;
            float4 v = src[((m0 + (size_t)m) << 7) + c4];
            uint2 p;
            p.x = h22u(__floats2half2_rn(v.x, v.y));
            p.y = h22u(__floats2half2_rn(v.z, v.w));
            *reinterpret_cast<uint2*>(smem + (SMEM_BANK + m * BANK_RS + c4 * 8)) = p;
        }
    }

    // ---- Prep: CTAs 0..127 normalize 8 queries each (warp per query) ----
    if (blockIdx.x < PREP_CTAS) {
        const int q = blockIdx.x * 8 + w;
        const float4* src = reinterpret_cast<const float4*>(feat + (size_t)q * DDIM);
        float4 v[4];
        float ss = 0.0f;
        #pragma unroll
        for (int p = 0; p < 4; ++p) {
            v[p] = src[p * 32 + lane];
            ss += v[p].x * v[p].x + v[p].y * v[p].y + v[p].z * v[p].z + v[p].w * v[p].w;
        }
        #pragma unroll
        for (int o = 16; o > 0; o >>= 1) ss += __shfl_xor_sync(0xFFFFFFFFu, ss, o);
        const float inv = rsqrtf(ss);
        __half2* dst = reinterpret_cast<__half2*>(g_qh + (size_t)q * DDIM);
        #pragma unroll
        for (int p = 0; p < 4; ++p) {
            dst[(p * 32 + lane) * 2 + 0] = __floats2half2_rn(v[p].x * inv, v[p].y * inv);
            dst[(p * 32 + lane) * 2 + 1] = __floats2half2_rn(v[p].z * inv, v[p].w * inv);
        }
        if (lane == 0) g_key[q] = 0u;
        __syncthreads();
        if (tid == 0) {
            __threadfence();                        // release g_qh/g_key
            atomicAdd((unsigned*)&g_prep_done, 1u);
        }
    }

    // ---- Acquire prep; stagger odd same-SM CTAs by ~half a chunk ----
    if (tid == 0) {
        while (g_prep_done < PREP_CTAS) __nanosleep(64);
        __threadfence();                            // acquire
        if (s_rank & 1u) {
            unsigned long long t0 = clock64();
            while (clock64() - t0 < SKEW_CYC) { }
        }
    }
    __syncthreads();                                // also orders bank smem stores

    // ---- Main GEMM loop: ring-2 query buffer, one barrier per chunk ----
    const uint32_t lm_row = (uint32_t)(lane & 15);
    const uint32_t lm_col = (uint32_t)((lane & 16) ? 16 : 0);
    const uint32_t a_lane = ((uint32_t)(wm * 32) + lm_row) * QBUF_RS + lm_col;
    const uint32_t b_lane = sb + SMEM_BANK + ((uint32_t)(wn * 32) + lm_row) * BANK_RS + lm_col;

    issue_qchunk(sb, tid, 0, 0);
    int j = 0;
    for (int pass = 0; pass < NPASS; ++pass) {
        uint32_t d[2][4][2];                        // [m-tile][n8-tile][row] f16x2
        #pragma unroll
        for (int mt = 0; mt < 2; ++mt)
            #pragma unroll
            for (int nt = 0; nt < 4; ++nt) { d[mt][nt][0] = 0u; d[mt][nt][1] = 0u; }

        for (int kc = 0; kc < KCH; ++kc, ++j) {
            CP_ASYNC_WAIT(0);                       // chunk j landed
            __syncthreads();                        // all warps done with slot j^1

            const uint32_t abase = sb + (uint32_t)(SMEM_QBUF + (j & 1) * QBUF_SZ) + a_lane;
            const uint32_t bbase = b_lane + (uint32_t)(kc * 128);

            // ks = 0 first, THEN issue next chunk's loads (MMAs start sooner)
            #pragma unroll
            for (int ks = 0; ks < 4; ++ks) {
                uint32_t a[2][4];
                #pragma unroll
                for (int mt = 0; mt < 2; ++mt)
                    LDMATRIX_X4(a[mt][0], a[mt][1], a[mt][2], a[mt][3],
                                abase + (uint32_t)(mt * 16 * QBUF_RS + ks * 32));
                #pragma unroll
                for (int bt = 0; bt < 2; ++bt) {
                    uint32_t b0, b1, b2, b3;        // b0/b2: n8 tile 2bt ; b1/b3: 2bt+1
                    LDMATRIX_X4(b0, b1, b2, b3,
                                bbase + (uint32_t)(bt * 16 * BANK_RS + ks * 32));
                    #pragma unroll
                    for (int mt = 0; mt < 2; ++mt) {
                        mma16816h(d[mt][2 * bt],     a[mt], b0, b2);
                        mma16816h(d[mt][2 * bt + 1], a[mt], b1, b3);
                    }
                }
                if (ks == 0 && j + 1 < NCHUNK)
                    issue_qchunk(sb, tid, j + 1, (j + 1) & 1);
            }
        }

        // ---- Epilogue: max over this warp's 32 bank rows per query ----
        #pragma unroll
        for (int mt = 0; mt < 2; ++mt) {
            __half2 h0 = u2h2(d[mt][0][0]);
            __half2 h1 = u2h2(d[mt][0][1]);
            #pragma unroll
            for (int nt = 1; nt < 4; ++nt) {
                h0 = __hmax2(h0, u2h2(d[mt][nt][0]));
                h1 = __hmax2(h1, u2h2(d[mt][nt][1]));
            }
            float mx0 = fmaxf(__low2float(h0), __high2float(h0));
            float mx1 = fmaxf(__low2float(h1), __high2float(h1));
            mx0 = fmaxf(mx0, __shfl_xor_sync(0xFFFFFFFFu, mx0, 1));
            mx0 = fmaxf(mx0, __shfl_xor_sync(0xFFFFFFFFu, mx0, 2));
            mx1 = fmaxf(mx1, __shfl_xor_sync(0xFFFFFFFFu, mx1, 1));
            mx1 = fmaxf(mx1, __shfl_xor_sync(0xFFFFFFFFu, mx1, 2));
            if ((lane & 3) == 0) {
                int q0 = pass * MEGA + wm * 32 + mt * 16 + (lane >> 2);
                atomicMax(&g_key[q0],     enc_key(mx0));
                atomicMax(&g_key[q0 + 8], enc_key(mx1));
            }
        }
    }

    // ---- Completion: last CTA decodes keys and resets counters ----
    __threadfence();                                // release atomicMax results
    __syncthreads();
    if (tid == 0) s_last = atomicAdd(&g_done, 1u);
    __syncthreads();
    if (s_last == NCTAS - 1) {
        __threadfence();                            // acquire all g_key updates
        volatile unsigned* keys = (volatile unsigned*)g_key;
        for (int i = tid; i < NQ; i += THREADS) {
            unsigned key = keys[i];
            unsigned bits = (key & 0x80000000u) ? (key ^ 0x80000000u) : ~key;
            float xy = __uint_as_float(bits);
            out[i] = sqrtf(fmaxf(2.0f - 2.0f * xy, 1e-12f));
        }
        for (int i = tid; i < 256; i += THREADS) g_smrank[i] = 0u;  // replay reset
        __syncthreads();
        if (tid == 0) {
            g_done = 0;
            *(unsigned*)&g_prep_done = 0;
        }
    }
}

// ============================================================================
// Launch: one kernel
// ============================================================================
extern "C" void kernel_launch(void* const* d_in, const int* in_sizes, int n_in,
                              void* d_out, int out_size) {
    const float* feat = (const float*)d_in[0];
    const float* bank = (const float*)d_in[1];
    if (n_in >= 2 && in_sizes[0] != NQ * DDIM) {   // robust to input ordering
        feat = (const float*)d_in[1];
        bank = (const float*)d_in[0];
    }
    float* out = (float*)d_out;

    cudaFuncSetAttribute(patchcore_all, cudaFuncAttributeMaxDynamicSharedMemorySize, SMEM_TOTAL);
    patchcore_all<<<NCTAS, THREADS, SMEM_TOTAL>>>(feat, bank, out);
}

// round 13
// speedup vs baseline: 1.3095x; 1.1409x over previous
#include <cuda_runtime.h>
#include <cuda_fp16.h>
#include <cstdint>

// ============================================================================
// Problem constants
// ============================================================================
#define NQ        1024
#define DDIM      512
#define MROWS     262144
#define BANK_TILE 64           // bank rows per CTA (2 CTAs/SM)
#define MEGA      128          // queries per pass
#define NPASS     8
#define KCH       8            // k-chunks of 64 dims per pass
#define NCHUNK    64
#define THREADS   256
#define NCTAS     (MROWS / BANK_TILE)   // 4096
#define PREP_CTAS 128
#define SKEW_CYC  1000

// smem layout. Row pads: 8-row ldmatrix strides hit distinct 16B groups.
#define BANK_RS    1040
#define QBUF_RS    144
#define SMEM_BANK  0
#define BANK_SZ    (BANK_TILE * BANK_RS)          // 66560
#define SMEM_QBUF  BANK_SZ
#define ABUF_SZ    (32 * QBUF_RS)                 // 4608 per (wm, slot)
#define SMEM_TOTAL (SMEM_QBUF + 8 * ABUF_SZ)      // 103424 -> 2 CTAs/SM

__device__ __align__(1024) __half g_qh[NQ * DDIM];
__device__ unsigned g_key[NQ];
__device__ volatile unsigned g_prep_done;   // prep-CTA arrival count
__device__ unsigned g_done;                 // finished-CTA count
__device__ unsigned g_smrank[256];          // per-SM arrival rank (stagger)

// ============================================================================
// Helpers
// ============================================================================
__device__ __forceinline__ uint32_t smem_to_u32(const void* p) {
    uint32_t a;
    asm("{ .reg .u64 t; cvta.to.shared.u64 t, %1; cvt.u32.u64 %0, t; }" : "=r"(a) : "l"(p));
    return a;
}
__device__ __forceinline__ uint32_t smid() {
    uint32_t s;
    asm("mov.u32 %0, %%smid;" : "=r"(s));
    return s;
}

#define CP_ASYNC16(dst_u32, src_gptr) \
    asm volatile("cp.async.cg.shared.global [%0], [%1], 16;" :: "r"(dst_u32), "l"(src_gptr) : "memory")
#define CP_ASYNC_COMMIT() asm volatile("cp.async.commit_group;" ::: "memory")
#define CP_ASYNC_WAIT(n)  asm volatile("cp.async.wait_group %0;" :: "n"(n) : "memory")
// SMSP-local pair barrier: warps {wm, wm+4} (64 threads), ids 1..4
#define PAIR_BAR(id)      asm volatile("bar.sync %0, 64;" :: "r"(id) : "memory")

#define LDMATRIX_X4(r0, r1, r2, r3, addr) \
    asm volatile("ldmatrix.sync.aligned.m8n8.x4.shared.b16 {%0,%1,%2,%3}, [%4];" \
        : "=r"(r0), "=r"(r1), "=r"(r2), "=r"(r3) : "r"(addr))

__device__ __forceinline__ void mma16816h(uint32_t* d, const uint32_t* a, uint32_t b0, uint32_t b1) {
    asm volatile(
        "mma.sync.aligned.m16n8k16.row.col.f16.f16.f16.f16 "
        "{%0,%1}, {%2,%3,%4,%5}, {%6,%7}, {%0,%1};"
        : "+r"(d[0]), "+r"(d[1])
        : "r"(a[0]), "r"(a[1]), "r"(a[2]), "r"(a[3]), "r"(b0), "r"(b1));
}

__device__ __forceinline__ __half2 u2h2(uint32_t u) { return *reinterpret_cast<__half2*>(&u); }
__device__ __forceinline__ uint32_t h22u(__half2 h) { return *reinterpret_cast<uint32_t*>(&h); }

__device__ __forceinline__ unsigned enc_key(float f) {
    unsigned b = __float_as_uint(f);
    return (b & 0x80000000u) ? ~b : (b | 0x80000000u);
}

// Pair loader: 32 query rows (wm-group) x 64 dims of chunk j -> (wm, slot).
// Both warps of the pair issue half (4 cp.async per thread), one group each.
__device__ __forceinline__ void issue_pair_chunk(uint32_t sb, int pairTid, int wm,
                                                 int j, int slot) {
    const int pass = j >> 3, kc = j & 7;
    const char* src_base = reinterpret_cast<const char*>(g_qh)
                         + (size_t)(pass * MEGA + wm * 32) * (DDIM * 2) + kc * 128;
    const uint32_t dst_base = sb + (uint32_t)(SMEM_QBUF + (wm * 2 + slot) * ABUF_SZ);
    #pragma unroll
    for (int it = 0; it < 4; ++it) {
        int idx = pairTid + it * 64;           // 256 granules of 16B (32 rows x 8)
        int n = idx >> 3, t = idx & 7;
        CP_ASYNC16(dst_base + (uint32_t)(n * QBUF_RS + t * 16),
                   src_base + (size_t)n * (DDIM * 2) + t * 16);
    }
    CP_ASYNC_COMMIT();
}

// ============================================================================
// Single fused kernel: prep -> flag -> pair-pipelined GEMM+max -> last CTA
// decodes. NO CTA barrier in the main loop: each wm-pair (both warps on the
// same SMSP) runs its own ring-2 A pipeline behind a 64-thread named barrier.
// ============================================================================
__global__ void __launch_bounds__(THREADS, 2)
patchcore_all(const float* __restrict__ feat, const float* __restrict__ bank,
              float* __restrict__ out) {
    extern __shared__ char smem[];
    __shared__ unsigned s_last;
    __shared__ unsigned s_rank;
    const uint32_t sb = smem_to_u32(smem);
    const int tid  = threadIdx.x;
    const int w    = tid >> 5;
    const int lane = tid & 31;
    const int wm   = w & 3;        // m-offset wm*32 (queries); == SMSP id
    const int wn   = w >> 2;       // n-offset wn*32 (bank rows)
    const int pairTid = wn * 32 + lane;   // 0..63 within the wm-pair
    const size_t m0 = (size_t)blockIdx.x * BANK_TILE;

    if (tid == 0) s_rank = atomicAdd(&g_smrank[smid() & 255], 1u);

    // ---- Bank tile (64 x 512 fp32) -> fp16 smem (independent of queries) ----
    {
        const float4* src = reinterpret_cast<const float4*>(bank);
        #pragma unroll 4
        for (int idx = tid; idx < BANK_TILE * (DDIM / 4); idx += THREADS) {
            int m = idx >> 7;
            int c4 = idx & 127;
            float4 v = src[((m0 + (size_t)m) << 7) + c4];
            uint2 p;
            p.x = h22u(__floats2half2_rn(v.x, v.y));
            p.y = h22u(__floats2half2_rn(v.z, v.w));
            *reinterpret_cast<uint2*>(smem + (SMEM_BANK + m * BANK_RS + c4 * 8)) = p;
        }
    }

    // ---- Prep: CTAs 0..127 normalize 8 queries each (warp per query) ----
    if (blockIdx.x < PREP_CTAS) {
        const int q = blockIdx.x * 8 + w;
        const float4* src = reinterpret_cast<const float4*>(feat + (size_t)q * DDIM);
        float4 v[4];
        float ss = 0.0f;
        #pragma unroll
        for (int p = 0; p < 4; ++p) {
            v[p] = src[p * 32 + lane];
            ss += v[p].x * v[p].x + v[p].y * v[p].y + v[p].z * v[p].z + v[p].w * v[p].w;
        }
        #pragma unroll
        for (int o = 16; o > 0; o >>= 1) ss += __shfl_xor_sync(0xFFFFFFFFu, ss, o);
        const float inv = rsqrtf(ss);
        __half2* dst = reinterpret_cast<__half2*>(g_qh + (size_t)q * DDIM);
        #pragma unroll
        for (int p = 0; p < 4; ++p) {
            dst[(p * 32 + lane) * 2 + 0] = __floats2half2_rn(v[p].x * inv, v[p].y * inv);
            dst[(p * 32 + lane) * 2 + 1] = __floats2half2_rn(v[p].z * inv, v[p].w * inv);
        }
        if (lane == 0) g_key[q] = 0u;
        __syncthreads();
        if (tid == 0) {
            __threadfence();                        // release g_qh/g_key
            atomicAdd((unsigned*)&g_prep_done, 1u);
        }
    }

    // ---- Acquire prep; stagger odd same-SM CTAs by ~half a chunk ----
    if (tid == 0) {
        while (g_prep_done < PREP_CTAS) __nanosleep(64);
        __threadfence();                            // acquire
        if (s_rank & 1u) {
            unsigned long long t0 = clock64();
            while (clock64() - t0 < SKEW_CYC) { }
        }
    }
    __syncthreads();                                // also orders bank smem stores

    // ---- Main GEMM loop: per-pair ring-2 A buffers, pair barriers only ----
    const uint32_t lm_row = (uint32_t)(lane & 15);
    const uint32_t lm_col = (uint32_t)((lane & 16) ? 16 : 0);
    const uint32_t a_lane = lm_row * QBUF_RS + lm_col;    // within pair A buffer
    const uint32_t b_lane = sb + SMEM_BANK + ((uint32_t)(wn * 32) + lm_row) * BANK_RS + lm_col;
    const int barid = wm + 1;

    issue_pair_chunk(sb, pairTid, wm, 0, 0);
    int j = 0;
    for (int pass = 0; pass < NPASS; ++pass) {
        uint32_t d[2][4][2];                        // [m-tile][n8-tile][row] f16x2
        #pragma unroll
        for (int mt = 0; mt < 2; ++mt)
            #pragma unroll
            for (int nt = 0; nt < 4; ++nt) { d[mt][nt][0] = 0u; d[mt][nt][1] = 0u; }

        for (int kc = 0; kc < KCH; ++kc, ++j) {
            CP_ASYNC_WAIT(0);                       // my half of chunk j landed
            PAIR_BAR(barid);                        // partner's half landed; both
                                                    // warps are past chunk j-1 reads
            if (j + 1 < NCHUNK)
                issue_pair_chunk(sb, pairTid, wm, j + 1, (j + 1) & 1);

            const uint32_t abase = sb + (uint32_t)(SMEM_QBUF + (wm * 2 + (j & 1)) * ABUF_SZ)
                                 + a_lane;
            const uint32_t bbase = b_lane + (uint32_t)(kc * 128);
            #pragma unroll
            for (int ks = 0; ks < 4; ++ks) {
                uint32_t a[2][4];
                #pragma unroll
                for (int mt = 0; mt < 2; ++mt)
                    LDMATRIX_X4(a[mt][0], a[mt][1], a[mt][2], a[mt][3],
                                abase + (uint32_t)(mt * 16 * QBUF_RS + ks * 32));
                #pragma unroll
                for (int bt = 0; bt < 2; ++bt) {
                    uint32_t b0, b1, b2, b3;        // b0/b2: n8 tile 2bt ; b1/b3: 2bt+1
                    LDMATRIX_X4(b0, b1, b2, b3,
                                bbase + (uint32_t)(bt * 16 * BANK_RS + ks * 32));
                    #pragma unroll
                    for (int mt = 0; mt < 2; ++mt) {
                        mma16816h(d[mt][2 * bt],     a[mt], b0, b2);
                        mma16816h(d[mt][2 * bt + 1], a[mt], b1, b3);
                    }
                }
            }
        }

        // ---- Epilogue: max over this warp's 32 bank rows per query ----
        #pragma unroll
        for (int mt = 0; mt < 2; ++mt) {
            __half2 h0 = u2h2(d[mt][0][0]);
            __half2 h1 = u2h2(d[mt][0][1]);
            #pragma unroll
            for (int nt = 1; nt < 4; ++nt) {
                h0 = __hmax2(h0, u2h2(d[mt][nt][0]));
                h1 = __hmax2(h1, u2h2(d[mt][nt][1]));
            }
            float mx0 = fmaxf(__low2float(h0), __high2float(h0));
            float mx1 = fmaxf(__low2float(h1), __high2float(h1));
            mx0 = fmaxf(mx0, __shfl_xor_sync(0xFFFFFFFFu, mx0, 1));
            mx0 = fmaxf(mx0, __shfl_xor_sync(0xFFFFFFFFu, mx0, 2));
            mx1 = fmaxf(mx1, __shfl_xor_sync(0xFFFFFFFFu, mx1, 1));
            mx1 = fmaxf(mx1, __shfl_xor_sync(0xFFFFFFFFu, mx1, 2));
            if ((lane & 3) == 0) {
                int q0 = pass * MEGA + wm * 32 + mt * 16 + (lane >> 2);
                atomicMax(&g_key[q0],     enc_key(mx0));
                atomicMax(&g_key[q0 + 8], enc_key(mx1));
            }
        }
    }

    // ---- Completion: last CTA decodes keys and resets counters ----
    __threadfence();                                // release atomicMax results
    __syncthreads();
    if (tid == 0) s_last = atomicAdd(&g_done, 1u);
    __syncthreads();
    if (s_last == NCTAS - 1) {
        __threadfence();                            // acquire all g_key updates
        volatile unsigned* keys = (volatile unsigned*)g_key;
        for (int i = tid; i < NQ; i += THREADS) {
            unsigned key = keys[i];
            unsigned bits = (key & 0x80000000u) ? (key ^ 0x80000000u) : ~key;
            float xy = __uint_as_float(bits);
            out[i] = sqrtf(fmaxf(2.0f - 2.0f * xy, 1e-12f));
        }
        for (int i = tid; i < 256; i += THREADS) g_smrank[i] = 0u;  // replay reset
        __syncthreads();
        if (tid == 0) {
            g_done = 0;
            *(unsigned*)&g_prep_done = 0;
        }
    }
}

// ============================================================================
// Launch: one kernel
// ============================================================================
extern "C" void kernel_launch(void* const* d_in, const int* in_sizes, int n_in,
                              void* d_out, int out_size) {
    const float* feat = (const float*)d_in[0];
    const float* bank = (const float*)d_in[1];
    if (n_in >= 2 && in_sizes[0] != NQ * DDIM) {   // robust to input ordering
        feat = (const float*)d_in[1];
        bank = (const float*)d_in[0];
    }
    float* out = (float*)d_out;

    cudaFuncSetAttribute(patchcore_all, cudaFuncAttributeMaxDynamicSharedMemorySize, SMEM_TOTAL);
    patchcore_all<<<NCTAS, THREADS, SMEM_TOTAL>>>(feat, bank, out);
}